// round 5
// baseline (speedup 1.0000x reference)
#include <cuda_runtime.h>
#include <cuda_bf16.h>
#include <math.h>

// Problem constants
#define NB   64
#define NT   512
#define NEMB 128
#define NHID 256
#define NMEL 80
#define NVOC 256
#define G4   1024      // 4*NHID
#define LMAX 1536      // safe upper bound on expanded length (expected ~800 max)

// ---------------- device scratch (static: no allocations allowed) ----------------
__device__ int   g_tok[NB * LMAX];                    // expanded token ids (NVOC == padding row)
__device__ float g_tab[2 * 257 * G4];                 // [dir][vocab(+pad)][gate-row] input proj + biases
__device__ int   g_flag[8 * 16];                      // [group(dir*4+chunk)][slice] = last finished step + 1
__device__ float g_h[2ull * LMAX * NHID * NB];        // [dir][l][u][b] hidden states (batch innermost)

// ---------------- packed f32x2 helpers ----------------
__device__ __forceinline__ unsigned long long pack2(float lo, float hi) {
    unsigned long long r;
    asm("mov.b64 %0, {%1, %2};" : "=l"(r) : "f"(lo), "f"(hi));
    return r;
}
__device__ __forceinline__ float2 unpack2(unsigned long long v) {
    float2 r;
    asm("mov.b64 {%0, %1}, %2;" : "=f"(r.x), "=f"(r.y) : "l"(v));
    return r;
}
__device__ __forceinline__ void ffma2(unsigned long long& d, unsigned long long a, unsigned long long b) {
    asm("fma.rn.f32x2 %0, %1, %2, %0;" : "+l"(d) : "l"(a), "l"(b));
}

// ---------------- K1: input-projection tables (embed @ wih.T + bih + bhh) ----------------
__global__ void k_tab(const float* __restrict__ embed,
                      const float* __restrict__ wih_f, const float* __restrict__ bih_f,
                      const float* __restrict__ bhh_f,
                      const float* __restrict__ wih_b, const float* __restrict__ bih_b,
                      const float* __restrict__ bhh_b) {
    int bid = blockIdx.x;          // 514 blocks: dir*257 + v
    int dir = bid / 257;
    int v   = bid % 257;
    const float* wih = dir ? wih_b : wih_f;
    const float* bih = dir ? bih_b : bih_f;
    const float* bhh = dir ? bhh_b : bhh_f;
    for (int r = threadIdx.x; r < G4; r += 256) {
        float a = bih[r] + bhh[r];
        if (v < NVOC) {
            const float* w = wih + r * NEMB;
            const float* e = embed + v * NEMB;
            #pragma unroll 8
            for (int k = 0; k < NEMB; k++) a += e[k] * w[k];
        }
        g_tab[dir * (257 * G4) + v * G4 + r] = a;
    }
}

// ---------------- K2: durations, cumsum, length-regulator expand (+ flag zero) ----------------
__global__ void k_expand(const int* __restrict__ x,
                         const float* __restrict__ embed,
                         const float* __restrict__ dp_w,
                         const float* __restrict__ dp_b, int L) {
    __shared__ int s_cum[NT];
    int b = blockIdx.x;
    int t = threadIdx.x;          // 512 threads
    if (b == 0 && t < 8 * 16) g_flag[t] = 0;        // zero step flags (graph replays!)
    int xv = x[b * NT + t];
    // duration projection for this token: relu(embed[xv] . dp_w + dp_b)
    float d = dp_b[0];
    const float* e = embed + xv * NEMB;
    #pragma unroll 8
    for (int k = 0; k < NEMB; k++) d += e[k] * dp_w[k];
    d = fmaxf(d, 0.f);
    int dur = (int)floorf(d) + 1;
    s_cum[t] = dur;
    __syncthreads();
    if (t == 0) {                 // tiny sequential scan (512 ints)
        int acc = 0;
        for (int i = 0; i < NT; i++) { acc += s_cum[i]; s_cum[i] = acc; }
    }
    __syncthreads();
    int end   = s_cum[t];
    int start = (t == 0) ? 0 : s_cum[t - 1];
    for (int p = start; p < end && p < L; p++) g_tok[b * LMAX + p] = xv;
    int len = s_cum[NT - 1];
    for (int p = len + t; p < L; p += NT) g_tok[b * LMAX + p] = NVOC;  // padding row
}

// ---------------- K3: persistent bidirectional LSTM ----------------
// MUFU-based transcendentals: __expf (EX2) + __fdividef (RCP+MUL), ~2ulp each.
__device__ __forceinline__ float sigm(float x)   { return __fdividef(1.f, 1.f + __expf(-x)); }
__device__ __forceinline__ float tanh_f(float x) { return 1.f - __fdividef(2.f, __expf(2.f * x) + 1.f); }

#define LSTM_SMEM (64 * 256 * 4 + 256 * 16 * 8)   // 64KB weights + 32KB duplicated h

__global__ void __launch_bounds__(128, 1)
k_lstm(const float* __restrict__ whh_f, const float* __restrict__ whh_b, int L) {
    extern __shared__ float sm[];
    float* w_smf = sm;                                    // [k=256][col=64], col = u_local*4 + gate
    unsigned long long* h2_sm =
        (unsigned long long*)(sm + 256 * 64);             // [k=256][b_local=16] duplicated (h,h)

    int bx    = blockIdx.x;         // 128 blocks (all resident: 128 <= 148 SMs)
    int dir   = bx >> 6;            // 0 fwd, 1 bwd
    int slice = (bx >> 2) & 15;     // 16 hidden-unit slices of 16 units
    int chunk = bx & 3;             // 4 batch chunks of 16
    int u0 = slice * 16, b0 = chunk * 16;
    int tid = threadIdx.x;          // 128 threads
    int ul = tid >> 3;              // 0..15  unit within slice
    int bp = tid & 7;               // 0..7   batch PAIR within chunk (2 cells/thread)
    int grp = dir * 4 + chunk;

    const float* whh = dir ? whh_b : whh_f;
    // Load whh slice k-major: w_smf[k*64 + u*4 + g] = whh[(g*NHID + u0+u)*NHID + k]
    for (int i = tid; i < 64 * 256; i += 128) {
        int col = i & 63, k = i >> 6;
        int u = col >> 2, g = col & 3;
        w_smf[k * 64 + col] = whh[(g * NHID + u0 + u) * NHID + k];
    }
    __syncthreads();

    const ulonglong2* wp  = (const ulonglong2*)w_smf + ul;   // + k*16 : (.x=(i,f), .y=(g,o)) of unit ul
    const ulonglong2* hp2 = (const ulonglong2*)h2_sm + bp;   // + k*8  : dup h of batches 2bp, 2bp+1
    const float* tabd  = g_tab + dir * (257 * G4);
    float* hout_base   = g_h + (size_t)dir * LMAX * NHID * NB;   // [l][u][b]

    int bg0 = b0 + 2 * bp;          // global batch of first cell
    int urow = u0 + ul;
    float c0 = 0.f, c1 = 0.f;

    for (int s = 0; s < L; s++) {
        int l = dir ? (L - 1 - s) : s;
        // tokens + table biases (independent of h -> overlap the flag wait)
        int tok0 = g_tok[bg0 * LMAX + l];
        int tok1 = g_tok[(bg0 + 1) * LMAX + l];
        const float* tr0 = tabd + tok0 * G4 + urow;
        const float* tr1 = tabd + tok1 * G4 + urow;
        unsigned long long aif0 = pack2(tr0[0],        tr0[NHID]);
        unsigned long long ago0 = pack2(tr0[2 * NHID], tr0[3 * NHID]);
        unsigned long long aif1 = pack2(tr1[0],        tr1[NHID]);
        unsigned long long ago1 = pack2(tr1[2 * NHID], tr1[3 * NHID]);

        if (s > 0) {
            int prev_l = dir ? (l + 1) : (l - 1);
            // wait: all 16 slices of this (dir, chunk) group finished step s-1
            if (tid < 16) {
                volatile int* f = g_flag + grp * 16 + tid;
                int guard = 0;
                while (*f < s) {
                    __nanosleep(32);                    // cut L2 poll traffic; cheap wakeup
                    if (++guard > (1 << 24)) break;
                }
                __threadfence();   // acquire
            }
            __syncthreads();
            // stage h(prev)[all 256 u][our 16 b], duplicated (h,h): LDG.64 + STS.128 per iter
            const float* hprev = hout_base + (size_t)prev_l * NHID * NB + b0;
            ulonglong2* h2v = (ulonglong2*)h2_sm;
            for (int i = tid; i < 256 * 8; i += 128) {
                int u = i >> 3, p = i & 7;                  // p fastest -> coalesced 64B segments
                float2 hv = *(const float2*)(hprev + u * NB + 2 * p);
                h2v[u * 8 + p] = make_ulonglong2(pack2(hv.x, hv.x), pack2(hv.y, hv.y));
            }
            __syncthreads();
            // gates += h @ whh_slice.T  (2 cells x 2 packed gate-pairs per k)
            #pragma unroll 8
            for (int k = 0; k < NHID; k++) {
                ulonglong2 w = wp[k * 16];
                ulonglong2 h = hp2[k * 8];
                ffma2(aif0, w.x, h.x);
                ffma2(ago0, w.y, h.x);
                ffma2(aif1, w.x, h.y);
                ffma2(ago1, w.y, h.y);
            }
        }
        // LSTM cells (PyTorch gate order i,f,g,o)
        float2 vif0 = unpack2(aif0), vgo0 = unpack2(ago0);
        float2 vif1 = unpack2(aif1), vgo1 = unpack2(ago1);
        c0 = sigm(vif0.y) * c0 + sigm(vif0.x) * tanh_f(vgo0.x);
        c1 = sigm(vif1.y) * c1 + sigm(vif1.x) * tanh_f(vgo1.x);
        float h0 = sigm(vgo0.y) * tanh_f(c0);
        float h1 = sigm(vgo1.y) * tanh_f(c1);
        *(float2*)(hout_base + (size_t)l * NHID * NB + urow * NB + bg0) = make_float2(h0, h1);
        __threadfence();           // release
        __syncthreads();
        if (tid == 0) *(volatile int*)(g_flag + grp * 16 + slice) = s + 1;
    }
}

// ---------------- K4: final linear (concat(hf,hb) @ lin_w.T + lin_b) ----------------
#define WPAD  68
#define HSPAD 516
#define FIN_SMEM (16 * HSPAD * 4 + NMEL * WPAD * 4)

__global__ void __launch_bounds__(256)
k_final(const float* __restrict__ lin_w, const float* __restrict__ lin_b,
        float* __restrict__ out, int L) {
    extern __shared__ float sm[];
    float* hs = sm;               // [16][HSPAD]  cols 0..255 = hf, 256..511 = hb
    float* ws = sm + 16 * HSPAD;  // [80][WPAD]
    int l = blockIdx.x, b0 = blockIdx.y * 16;
    int tid = threadIdx.x;
    const float* hf = g_h + (size_t)l * NHID * NB + b0;                           // [u][b]
    const float* hb = g_h + (size_t)LMAX * NHID * NB + (size_t)l * NHID * NB + b0;
    for (int i = tid; i < 256 * 16; i += 256) {
        int u = i >> 4, bb = i & 15;              // b fastest -> coalesced 64B segments
        hs[bb * HSPAD + u]       = hf[u * NB + bb];
        hs[bb * HSPAD + 256 + u] = hb[u * NB + bb];
    }
    float acc[5] = {0, 0, 0, 0, 0};
    int ob[5], om[5];
    #pragma unroll
    for (int j = 0; j < 5; j++) { int o = tid + 256 * j; ob[j] = o / NMEL; om[j] = o % NMEL; }
    for (int kc = 0; kc < 512; kc += 64) {
        __syncthreads();
        for (int i = tid; i < NMEL * 64; i += 256) {
            int m = i >> 6, kk = i & 63;
            ws[m * WPAD + kk] = lin_w[m * 512 + kc + kk];
        }
        __syncthreads();
        #pragma unroll
        for (int j = 0; j < 5; j++) {
            const float* hp = hs + ob[j] * HSPAD + kc;
            const float* wq = ws + om[j] * WPAD;
            float a = acc[j];
            #pragma unroll
            for (int kk = 0; kk < 64; kk += 4) {
                float4 hv = *(const float4*)(hp + kk);
                float4 wv = *(const float4*)(wq + kk);
                a += hv.x * wv.x + hv.y * wv.y + hv.z * wv.z + hv.w * wv.w;
            }
            acc[j] = a;
        }
    }
    #pragma unroll
    for (int j = 0; j < 5; j++)
        out[(size_t)(b0 + ob[j]) * L * NMEL + (size_t)l * NMEL + om[j]] = acc[j] + lin_b[om[j]];
}

// ---------------- launch ----------------
extern "C" void kernel_launch(void* const* d_in, const int* in_sizes, int n_in,
                              void* d_out, int out_size) {
    const int*   x      = (const int*)  d_in[0];
    const float* embed  = (const float*)d_in[1];
    const float* dp_w   = (const float*)d_in[2];
    const float* dp_b   = (const float*)d_in[3];
    const float* wih_f  = (const float*)d_in[4];
    const float* whh_f  = (const float*)d_in[5];
    const float* bih_f  = (const float*)d_in[6];
    const float* bhh_f  = (const float*)d_in[7];
    const float* wih_b  = (const float*)d_in[8];
    const float* whh_b  = (const float*)d_in[9];
    const float* bih_b  = (const float*)d_in[10];
    const float* bhh_b  = (const float*)d_in[11];
    const float* lin_w  = (const float*)d_in[12];
    const float* lin_b  = (const float*)d_in[13];
    float* out = (float*)d_out;

    int L = out_size / (NB * NMEL);
    if (L > LMAX) L = LMAX;
    if (L < 1)    L = 1;

    cudaFuncSetAttribute(k_lstm,  cudaFuncAttributeMaxDynamicSharedMemorySize, LSTM_SMEM);
    cudaFuncSetAttribute(k_final, cudaFuncAttributeMaxDynamicSharedMemorySize, FIN_SMEM);

    k_tab   <<<514, 256>>>(embed, wih_f, bih_f, bhh_f, wih_b, bih_b, bhh_b);
    k_expand<<<NB, NT>>>(x, embed, dp_w, dp_b, L);
    k_lstm  <<<128, 128, LSTM_SMEM>>>(whh_f, whh_b, L);
    k_final <<<dim3(L, 4), 256, FIN_SMEM>>>(lin_w, lin_b, out, L);
}

// round 10
// speedup vs baseline: 1.4809x; 1.4809x over previous
#include <cuda_runtime.h>
#include <cuda_bf16.h>
#include <math.h>

// Problem constants
#define NB   64
#define NT   512
#define NEMB 128
#define NHID 256
#define NMEL 80
#define NVOC 256
#define G4   1024      // 4*NHID
#define LMAX 1536      // safe upper bound on expanded length (measured L=626)

// ---------------- device scratch (static: no allocations allowed) ----------------
__device__ int   g_tok[NB * LMAX];                    // expanded token ids (NVOC == padding row)
__device__ float g_tab[2 * 257 * G4];                 // [dir][vocab(+pad)][gate-row] input proj + biases
__device__ int   g_flag[8 * 16];                      // [group(dir*4+chunk)][slice] = last finished step + 1
__device__ float g_h[2ull * LMAX * NHID * NB];        // [dir][l][u][b] hidden states (batch innermost)

// ---------------- packed f32x2 + scoped sync helpers ----------------
__device__ __forceinline__ unsigned long long pack2(float lo, float hi) {
    unsigned long long r;
    asm("mov.b64 %0, {%1, %2};" : "=l"(r) : "f"(lo), "f"(hi));
    return r;
}
__device__ __forceinline__ float2 unpack2(unsigned long long v) {
    float2 r;
    asm("mov.b64 {%0, %1}, %2;" : "=f"(r.x), "=f"(r.y) : "l"(v));
    return r;
}
__device__ __forceinline__ void ffma2(unsigned long long& d, unsigned long long a, unsigned long long b) {
    asm("fma.rn.f32x2 %0, %1, %2, %0;" : "+l"(d) : "l"(a), "l"(b));
}
__device__ __forceinline__ void add2(unsigned long long& d, unsigned long long a) {
    asm("add.rn.f32x2 %0, %0, %1;" : "+l"(d) : "l"(a));
}
__device__ __forceinline__ int ld_acq(const int* p) {
    int v; asm volatile("ld.global.acquire.gpu.b32 %0, [%1];" : "=r"(v) : "l"(p) : "memory");
    return v;
}
__device__ __forceinline__ void st_rel(int* p, int v) {
    asm volatile("st.global.release.gpu.b32 [%0], %1;" :: "l"(p), "r"(v) : "memory");
}

// ---------------- K1: input-projection tables (embed @ wih.T + bih + bhh) ----------------
__global__ void k_tab(const float* __restrict__ embed,
                      const float* __restrict__ wih_f, const float* __restrict__ bih_f,
                      const float* __restrict__ bhh_f,
                      const float* __restrict__ wih_b, const float* __restrict__ bih_b,
                      const float* __restrict__ bhh_b) {
    int bid = blockIdx.x;          // 514 blocks: dir*257 + v
    int dir = bid / 257;
    int v   = bid % 257;
    const float* wih = dir ? wih_b : wih_f;
    const float* bih = dir ? bih_b : bih_f;
    const float* bhh = dir ? bhh_b : bhh_f;
    for (int r = threadIdx.x; r < G4; r += 256) {
        float a = bih[r] + bhh[r];
        if (v < NVOC) {
            const float* w = wih + r * NEMB;
            const float* e = embed + v * NEMB;
            #pragma unroll 8
            for (int k = 0; k < NEMB; k++) a += e[k] * w[k];
        }
        g_tab[dir * (257 * G4) + v * G4 + r] = a;
    }
}

// ---------------- K2: durations, cumsum, length-regulator expand (+ flag zero) ----------------
__global__ void k_expand(const int* __restrict__ x,
                         const float* __restrict__ embed,
                         const float* __restrict__ dp_w,
                         const float* __restrict__ dp_b, int L) {
    __shared__ int s_cum[NT];
    int b = blockIdx.x;
    int t = threadIdx.x;          // 512 threads
    if (b == 0 && t < 8 * 16) g_flag[t] = 0;        // zero step flags (graph replays!)
    int xv = x[b * NT + t];
    float d = dp_b[0];
    const float* e = embed + xv * NEMB;
    #pragma unroll 8
    for (int k = 0; k < NEMB; k++) d += e[k] * dp_w[k];
    d = fmaxf(d, 0.f);
    int dur = (int)floorf(d) + 1;
    s_cum[t] = dur;
    __syncthreads();
    if (t == 0) {                 // tiny sequential scan (512 ints)
        int acc = 0;
        for (int i = 0; i < NT; i++) { acc += s_cum[i]; s_cum[i] = acc; }
    }
    __syncthreads();
    int end   = s_cum[t];
    int start = (t == 0) ? 0 : s_cum[t - 1];
    for (int p = start; p < end && p < L; p++) g_tok[b * LMAX + p] = xv;
    int len = s_cum[NT - 1];
    for (int p = len + t; p < L; p += NT) g_tok[b * LMAX + p] = NVOC;  // padding row
}

// ---------------- K3: persistent bidirectional LSTM (512 thr, 4-way k-split) ----------------
__device__ __forceinline__ float sigm(float x)   { return __fdividef(1.f, 1.f + __expf(-x)); }
__device__ __forceinline__ float tanh_f(float x) { return 1.f - __fdividef(2.f, __expf(2.f * x) + 1.f); }

// 64KB weights + 32KB duplicated h + 12KB k-split reduction  (~108KB < 228KB carveout)
#define LSTM_SMEM (64 * 256 * 4 + 256 * 16 * 8 + 3 * 128 * 4 * 8)

__global__ void __launch_bounds__(512, 1)
k_lstm(const float* __restrict__ whh_f, const float* __restrict__ whh_b, int L) {
    extern __shared__ float sm[];
    float* w_smf = sm;                                    // [k=256][col=64], col = u_local*4 + gate
    unsigned long long* h2_sm =
        (unsigned long long*)(sm + 256 * 64);             // [k=256][b_local=16] duplicated (h,h)
    unsigned long long* red_sm = h2_sm + 256 * 16;        // [3][128][4] k-split partial gate sums

    int bx    = blockIdx.x;         // 128 blocks (all resident: 128 <= 148 SMs)
    int dir   = bx >> 6;            // 0 fwd, 1 bwd
    int slice = (bx >> 2) & 15;     // 16 hidden-unit slices of 16 units
    int chunk = bx & 3;             // 4 batch chunks of 16
    int u0 = slice * 16, b0 = chunk * 16;
    int tid = threadIdx.x;          // 512 threads, 16 warps (4 warps per SMSP)
    int kq = tid >> 7;              // k-quarter 0..3 (64 k-values each)
    int ul = (tid >> 3) & 15;       // unit within slice
    int bp = tid & 7;               // batch PAIR within chunk (2 cells/thread)
    int grp = dir * 4 + chunk;

    const float* whh = dir ? whh_b : whh_f;
    // Load whh slice k-major: w_smf[k*64 + u*4 + g] = whh[(g*NHID + u0+u)*NHID + k]
    for (int i = tid; i < 64 * 256; i += 512) {
        int col = i & 63, k = i >> 6;
        int u = col >> 2, g = col & 3;
        w_smf[k * 64 + col] = whh[(g * NHID + u0 + u) * NHID + k];
    }
    __syncthreads();

    const ulonglong2* wpk = (const ulonglong2*)w_smf + kq * 64 * 16 + ul;  // + k*16, k<64
    const ulonglong2* hpk = (const ulonglong2*)h2_sm + kq * 64 * 8 + bp;   // + k*8,  k<64
    const float* tabd  = g_tab + dir * (257 * G4);
    float* hout_base   = g_h + (size_t)dir * LMAX * NHID * NB;   // [l][u][b]

    int bg0 = b0 + 2 * bp;          // global batch of first cell
    int urow = u0 + ul;
    int rix  = (ul * 8 + bp) * 4;   // reduction slot (x4 u64)
    float c0 = 0.f, c1 = 0.f;

    for (int s = 0; s < L; s++) {
        int l = dir ? (L - 1 - s) : s;
        unsigned long long aif0 = 0, ago0 = 0, aif1 = 0, ago1 = 0;
        if (kq == 0) {
            // tokens + table biases (only quarter 0 seeds the bias; overlaps flag wait)
            int tok0 = g_tok[bg0 * LMAX + l];
            int tok1 = g_tok[(bg0 + 1) * LMAX + l];
            const float* tr0 = tabd + tok0 * G4 + urow;
            const float* tr1 = tabd + tok1 * G4 + urow;
            aif0 = pack2(tr0[0],        tr0[NHID]);
            ago0 = pack2(tr0[2 * NHID], tr0[3 * NHID]);
            aif1 = pack2(tr1[0],        tr1[NHID]);
            ago1 = pack2(tr1[2 * NHID], tr1[3 * NHID]);
        }

        if (s > 0) {
            int prev_l = dir ? (l + 1) : (l - 1);
            // wait: all 16 slices of this (dir, chunk) group finished step s-1
            if (tid < 16) {
                const int* f = g_flag + grp * 16 + tid;
                int it = 0;
                while (ld_acq(f) < s) {
                    if (++it > 64) __nanosleep(64);
                    if (it > (1 << 24)) break;
                }
            }
            __syncthreads();                                        // [A]
            // stage h(prev)[all 256 u][our 16 b], duplicated (h,h): LDG.64 + STS.128
            const float* hprev = hout_base + (size_t)prev_l * NHID * NB + b0;
            ulonglong2* h2v = (ulonglong2*)h2_sm;
            for (int i = tid; i < 256 * 8; i += 512) {
                int u = i >> 3, p = i & 7;                  // p fastest -> coalesced 64B segments
                float2 hv = *(const float2*)(hprev + u * NB + 2 * p);
                h2v[u * 8 + p] = make_ulonglong2(pack2(hv.x, hv.x), pack2(hv.y, hv.y));
            }
            __syncthreads();                                        // [B]
            // gates += h @ whh_slice.T over this warp's k-quarter (2 cells x 2 packed pairs)
            #pragma unroll 8
            for (int k = 0; k < 64; k++) {
                ulonglong2 w = wpk[k * 16];
                ulonglong2 h = hpk[k * 8];
                ffma2(aif0, w.x, h.x);
                ffma2(ago0, w.y, h.x);
                ffma2(aif1, w.x, h.y);
                ffma2(ago1, w.y, h.y);
            }
            // k-split reduction: quarters 1..3 publish, quarter 0 accumulates
            if (kq) {
                ulonglong2* r2 = (ulonglong2*)(red_sm + (kq - 1) * 512 + rix);
                r2[0] = make_ulonglong2(aif0, ago0);
                r2[1] = make_ulonglong2(aif1, ago1);
            }
            __syncthreads();                                        // [C]
            if (!kq) {
                #pragma unroll
                for (int q = 0; q < 3; q++) {
                    const ulonglong2* r2 = (const ulonglong2*)(red_sm + q * 512 + rix);
                    ulonglong2 p0 = r2[0], p1 = r2[1];
                    add2(aif0, p0.x); add2(ago0, p0.y);
                    add2(aif1, p1.x); add2(ago1, p1.y);
                }
            }
        }
        if (!kq) {
            // LSTM cells (PyTorch gate order i,f,g,o)
            float2 vif0 = unpack2(aif0), vgo0 = unpack2(ago0);
            float2 vif1 = unpack2(aif1), vgo1 = unpack2(ago1);
            c0 = sigm(vif0.y) * c0 + sigm(vif0.x) * tanh_f(vgo0.x);
            c1 = sigm(vif1.y) * c1 + sigm(vif1.x) * tanh_f(vgo1.x);
            float h0 = sigm(vgo0.y) * tanh_f(c0);
            float h1 = sigm(vgo1.y) * tanh_f(c1);
            *(float2*)(hout_base + (size_t)l * NHID * NB + urow * NB + bg0) = make_float2(h0, h1);
            // named barrier over the 4 compute warps only (all h stores come from tid 0..127);
            // the 12 k-split warps are already parked at next step's [A] (barrier 0 - independent)
            asm volatile("bar.sync 1, 128;" ::: "memory");
            if (tid == 0) st_rel(g_flag + grp * 16 + slice, s + 1);   // cumulative release
        }
    }
}

// ---------------- K4: final linear (concat(hf,hb) @ lin_w.T + lin_b) ----------------
#define WPAD  68
#define HSPAD 516
#define FIN_SMEM (16 * HSPAD * 4 + NMEL * WPAD * 4)

__global__ void __launch_bounds__(256)
k_final(const float* __restrict__ lin_w, const float* __restrict__ lin_b,
        float* __restrict__ out, int L) {
    extern __shared__ float sm[];
    float* hs = sm;               // [16][HSPAD]  cols 0..255 = hf, 256..511 = hb
    float* ws = sm + 16 * HSPAD;  // [80][WPAD]
    int l = blockIdx.x, b0 = blockIdx.y * 16;
    int tid = threadIdx.x;
    int bl   = tid >> 4;          // batch 0..15
    int mg   = tid & 15;          // mel group: mels mg*5 .. mg*5+4
    const float* hf = g_h + (size_t)l * NHID * NB + b0;                           // [u][b]
    const float* hb = g_h + (size_t)LMAX * NHID * NB + (size_t)l * NHID * NB + b0;
    for (int i = tid; i < 256 * 16; i += 256) {
        int u = i >> 4, bb = i & 15;              // b fastest -> coalesced 64B segments
        hs[bb * HSPAD + u]       = hf[u * NB + bb];
        hs[bb * HSPAD + 256 + u] = hb[u * NB + bb];
    }
    float acc[5] = {0, 0, 0, 0, 0};
    for (int kc = 0; kc < 512; kc += 64) {
        __syncthreads();
        for (int i = tid; i < NMEL * 64; i += 256) {
            int m = i >> 6, kk = i & 63;
            ws[m * WPAD + kk] = lin_w[m * 512 + kc + kk];
        }
        __syncthreads();
        const float* hrow = hs + bl * HSPAD + kc;
        #pragma unroll 4
        for (int kk = 0; kk < 64; kk += 4) {
            float4 hv = *(const float4*)(hrow + kk);      // one h vector, reused 5x
            #pragma unroll
            for (int j = 0; j < 5; j++) {
                float4 wv = *(const float4*)(ws + (mg * 5 + j) * WPAD + kk);
                acc[j] += hv.x * wv.x + hv.y * wv.y + hv.z * wv.z + hv.w * wv.w;
            }
        }
    }
    #pragma unroll
    for (int j = 0; j < 5; j++) {
        int m = mg * 5 + j;
        out[(size_t)(b0 + bl) * L * NMEL + (size_t)l * NMEL + m] = acc[j] + lin_b[m];
    }
}

// ---------------- launch ----------------
extern "C" void kernel_launch(void* const* d_in, const int* in_sizes, int n_in,
                              void* d_out, int out_size) {
    const int*   x      = (const int*)  d_in[0];
    const float* embed  = (const float*)d_in[1];
    const float* dp_w   = (const float*)d_in[2];
    const float* dp_b   = (const float*)d_in[3];
    const float* wih_f  = (const float*)d_in[4];
    const float* whh_f  = (const float*)d_in[5];
    const float* bih_f  = (const float*)d_in[6];
    const float* bhh_f  = (const float*)d_in[7];
    const float* wih_b  = (const float*)d_in[8];
    const float* whh_b  = (const float*)d_in[9];
    const float* bih_b  = (const float*)d_in[10];
    const float* bhh_b  = (const float*)d_in[11];
    const float* lin_w  = (const float*)d_in[12];
    const float* lin_b  = (const float*)d_in[13];
    float* out = (float*)d_out;

    int L = out_size / (NB * NMEL);
    if (L > LMAX) L = LMAX;
    if (L < 1)    L = 1;

    cudaFuncSetAttribute(k_lstm,  cudaFuncAttributeMaxDynamicSharedMemorySize, LSTM_SMEM);
    cudaFuncSetAttribute(k_final, cudaFuncAttributeMaxDynamicSharedMemorySize, FIN_SMEM);

    k_tab   <<<514, 256>>>(embed, wih_f, bih_f, bhh_f, wih_b, bih_b, bhh_b);
    k_expand<<<NB, NT>>>(x, embed, dp_w, dp_b, L);
    k_lstm  <<<128, 512, LSTM_SMEM>>>(whh_f, whh_b, L);
    k_final <<<dim3(L, 4), 256, FIN_SMEM>>>(lin_w, lin_b, out, L);
}